// round 2
// baseline (speedup 1.0000x reference)
#include <cuda_runtime.h>
#include <cuda_bf16.h>
#include <cstdint>
#include <cstddef>

#define NH 16
#define DK 64
#define DV 64
#define DM 1024
#define BB 2
#define SS 2048

#define HB   (NH * BB)            // 32
#define ROWS (BB * SS)            // 4096
#define OUT_E (ROWS * DM)         // 4,194,304 floats
#define ATT_E ((size_t)HB * SS * SS) // 134,217,728 floats

// ---------------- scratch (no allocations allowed) ----------------
__device__ float g_q[HB * SS * DK];        // 16 MB  q[h][b][s][k]
__device__ float g_k[HB * SS * DK];        // 16 MB
__device__ float g_v[HB * SS * DV];        // 16 MB
__device__ float g_pre[ROWS * NH * DV];    // 16 MB  pre[b][s][h*64+dv]
__device__ float g_rinv[HB * SS];          // per attn row 1/sum
__device__ int   g_mask[ROWS];             // mask[b][key]

// ---------------- mask conversion (dtype-robust) ----------------
__global__ void mask_kernel(const void* mraw, int n) {
    __shared__ int mode; // 0=u8, 1=i32, 2=f32
    if (threadIdx.x == 0) {
        const unsigned* mi = (const unsigned*)mraw;
        const float* mf = (const float*)mraw;
        int lim = n / 4; if (lim > 1024) lim = 1024;
        int ok_i = 1, ok_f = 1;
        for (int i = 0; i < lim; i++) {
            unsigned v = mi[i];
            if (v > 1u) ok_i = 0;
            float f = mf[i];
            if (!(f == 0.0f || f == 1.0f)) ok_f = 0;
            if (!ok_i && !ok_f) break;
        }
        mode = ok_i ? 1 : (ok_f ? 2 : 0);
    }
    __syncthreads();
    int md = mode;
    for (int i = threadIdx.x; i < n; i += blockDim.x) {
        int val;
        if (md == 1)      val = ((const int*)mraw)[i] != 0;
        else if (md == 2) val = ((const float*)mraw)[i] != 0.0f;
        else              val = ((const unsigned char*)mraw)[i] != 0;
        g_mask[i] = val;
    }
}

// outer-product accumulate: acc[i][j] += av[i] * bv[j]  (16 FFMA)
__device__ __forceinline__ void fma4x4(float (&acc)[4][4], const float4 av, const float4 bv) {
    acc[0][0] += av.x * bv.x; acc[0][1] += av.x * bv.y; acc[0][2] += av.x * bv.z; acc[0][3] += av.x * bv.w;
    acc[1][0] += av.y * bv.x; acc[1][1] += av.y * bv.y; acc[1][2] += av.y * bv.z; acc[1][3] += av.y * bv.w;
    acc[2][0] += av.z * bv.x; acc[2][1] += av.z * bv.y; acc[2][2] += av.z * bv.z; acc[2][3] += av.z * bv.w;
    acc[3][0] += av.w * bv.x; acc[3][1] += av.w * bv.y; acc[3][2] += av.w * bv.z; acc[3][3] += av.w * bv.w;
}

// ---------------- per-head projection GEMM ----------------
// C[((h*BB+b)*SS + s)][0..63] = X[b*SS+s][:] @ W[h]  (W[h] is DM x 64, row-major)
// grid: (ROWS/64, NH), block 256
__global__ __launch_bounds__(256) void proj_kernel(const float* __restrict__ X,
                                                   const float* __restrict__ W,
                                                   float* __restrict__ C) {
    const int h = blockIdx.y;
    const int m0 = blockIdx.x * 64;
    __shared__ float AsT[16][68]; // [k][m]
    __shared__ float Ws[16][68];  // [k][n]
    const int tid = threadIdx.x;
    const int tx = tid & 15, ty = tid >> 4;
    float acc[4][4] = {};
    const float* Wh = W + (size_t)h * DM * DK;

    for (int k0 = 0; k0 < DM; k0 += 16) {
        int e = tid * 4;
        // A tile 64x16 -> transposed smem
        {
            int m = e >> 4, kk = e & 15;
            float4 a = *(const float4*)(X + (size_t)(m0 + m) * DM + k0 + kk);
            AsT[kk + 0][m] = a.x; AsT[kk + 1][m] = a.y;
            AsT[kk + 2][m] = a.z; AsT[kk + 3][m] = a.w;
        }
        // W tile 16x64 -> direct
        {
            int kk = e >> 6, nn = e & 63;
            float4 w4 = *(const float4*)(Wh + (size_t)(k0 + kk) * DK + nn);
            *(float4*)&Ws[kk][nn] = w4;
        }
        __syncthreads();
#pragma unroll
        for (int kk = 0; kk < 16; kk++) {
            float4 av = *(const float4*)&AsT[kk][ty * 4];
            float4 bv = *(const float4*)&Ws[kk][tx * 4];
            fma4x4(acc, av, bv);
        }
        __syncthreads();
    }
    const int b = m0 / SS;
    const int s0 = m0 - b * SS;
    const size_t rbase = (size_t)(h * BB + b) * SS + s0;
#pragma unroll
    for (int i = 0; i < 4; i++) {
        float4 o = make_float4(acc[i][0], acc[i][1], acc[i][2], acc[i][3]);
        *(float4*)(C + (rbase + ty * 4 + i) * DK + tx * 4) = o;
    }
}

// ---------------- attention: scores + exp + mask + PV accumulate ----------------
// grid: (SS/64, BB, NH), block 256, dynamic smem
__global__ __launch_bounds__(256) void attn_kernel(float* __restrict__ attn) {
    extern __shared__ float smem[];
    float* qT = smem;                 // [64][68]  d-major: qT[d*68+q]
    float* kT = qT + 64 * 68;         // [64][68]  d-major
    float* Vs = kT + 64 * 68;         // [64][68]  key-major: Vs[key*68+dv]
    float* Es = Vs + 64 * 68;         // [64][65]  Es[q*65+key]
    int*  msk = (int*)(Es + 64 * 65); // [64]

    const int h = blockIdx.z, b = blockIdx.y;
    const int q0 = blockIdx.x * 64;
    const int tid = threadIdx.x;
    const int tx = tid & 15, ty = tid >> 4;

    const float* qbase = g_q + (size_t)(h * BB + b) * SS * DK;
    const float* kbase = g_k + (size_t)(h * BB + b) * SS * DK;
    const float* vbase = g_v + (size_t)(h * BB + b) * SS * DV;

    // load q tile transposed
    for (int e = tid * 4; e < 64 * 64; e += 1024) {
        int r = e >> 6, d = e & 63;
        float4 f = *(const float4*)(qbase + (size_t)(q0 + r) * DK + d);
        qT[(d + 0) * 68 + r] = f.x; qT[(d + 1) * 68 + r] = f.y;
        qT[(d + 2) * 68 + r] = f.z; qT[(d + 3) * 68 + r] = f.w;
    }

    float oacc[4][4] = {};
    float rs[4] = {};
    const float scale = 0.125f; // 1/sqrt(64)

    for (int kt = 0; kt < SS; kt += 64) {
        // load k (transposed) and v tiles
        for (int e = tid * 4; e < 64 * 64; e += 1024) {
            int r = e >> 6, d = e & 63;
            float4 f = *(const float4*)(kbase + (size_t)(kt + r) * DK + d);
            kT[(d + 0) * 68 + r] = f.x; kT[(d + 1) * 68 + r] = f.y;
            kT[(d + 2) * 68 + r] = f.z; kT[(d + 3) * 68 + r] = f.w;
            float4 g = *(const float4*)(vbase + (size_t)(kt + r) * DV + d);
            *(float4*)&Vs[r * 68 + d] = g;
        }
        if (tid < 64) msk[tid] = g_mask[b * SS + kt + tid];
        __syncthreads();

        // QK^T
        float sacc[4][4] = {};
#pragma unroll 8
        for (int d = 0; d < 64; d++) {
            float4 qa = *(const float4*)&qT[d * 68 + ty * 4];
            float4 kb = *(const float4*)&kT[d * 68 + tx * 4];
            fma4x4(sacc, qa, kb);
        }

        // exp + mask, write Es + global (unnormalized), accumulate row sums
        int ma = msk[tx * 4 + 0], mb = msk[tx * 4 + 1], mc = msk[tx * 4 + 2], md = msk[tx * 4 + 3];
#pragma unroll
        for (int i = 0; i < 4; i++) {
            float e0 = ma ? __expf(sacc[i][0] * scale) : 0.0f;
            float e1 = mb ? __expf(sacc[i][1] * scale) : 0.0f;
            float e2 = mc ? __expf(sacc[i][2] * scale) : 0.0f;
            float e3 = md ? __expf(sacc[i][3] * scale) : 0.0f;
            rs[i] += (e0 + e1) + (e2 + e3);
            int q = ty * 4 + i;
            Es[q * 65 + tx * 4 + 0] = e0; Es[q * 65 + tx * 4 + 1] = e1;
            Es[q * 65 + tx * 4 + 2] = e2; Es[q * 65 + tx * 4 + 3] = e3;
            if (attn) {
                size_t row = (size_t)(h * BB + b) * SS + q0 + q;
                *(float4*)(attn + row * SS + kt + tx * 4) = make_float4(e0, e1, e2, e3);
            }
        }
        __syncthreads();

        // PV: oacc += Es @ Vs
#pragma unroll 8
        for (int k = 0; k < 64; k++) {
            float e0 = Es[(ty * 4 + 0) * 65 + k];
            float e1 = Es[(ty * 4 + 1) * 65 + k];
            float e2 = Es[(ty * 4 + 2) * 65 + k];
            float e3 = Es[(ty * 4 + 3) * 65 + k];
            float4 vv = *(const float4*)&Vs[k * 68 + tx * 4];
            oacc[0][0] += e0 * vv.x; oacc[0][1] += e0 * vv.y; oacc[0][2] += e0 * vv.z; oacc[0][3] += e0 * vv.w;
            oacc[1][0] += e1 * vv.x; oacc[1][1] += e1 * vv.y; oacc[1][2] += e1 * vv.z; oacc[1][3] += e1 * vv.w;
            oacc[2][0] += e2 * vv.x; oacc[2][1] += e2 * vv.y; oacc[2][2] += e2 * vv.z; oacc[2][3] += e2 * vv.w;
            oacc[3][0] += e3 * vv.x; oacc[3][1] += e3 * vv.y; oacc[3][2] += e3 * vv.z; oacc[3][3] += e3 * vv.w;
        }
        __syncthreads();
    }

    // reduce rs across the 16 threads sharing ty (lanes 0-15 / 16-31 of each warp)
    float inv[4];
#pragma unroll
    for (int i = 0; i < 4; i++) {
        float v = rs[i];
        v += __shfl_xor_sync(0xffffffffu, v, 8, 16);
        v += __shfl_xor_sync(0xffffffffu, v, 4, 16);
        v += __shfl_xor_sync(0xffffffffu, v, 2, 16);
        v += __shfl_xor_sync(0xffffffffu, v, 1, 16);
        inv[i] = (v > 0.0f) ? (1.0f / v) : 0.0f;
    }
#pragma unroll
    for (int i = 0; i < 4; i++) {
        float iv = inv[i];
        float4 o = make_float4(oacc[i][0] * iv, oacc[i][1] * iv, oacc[i][2] * iv, oacc[i][3] * iv);
        *(float4*)(g_pre + ((size_t)(b * SS + q0 + ty * 4 + i)) * (NH * DV) + h * DV + tx * 4) = o;
    }
    if (tx == 0) {
#pragma unroll
        for (int i = 0; i < 4; i++)
            g_rinv[(size_t)(h * BB + b) * SS + q0 + ty * 4 + i] = inv[i];
    }
}

// ---------------- attn normalization pass ----------------
__global__ __launch_bounds__(256) void norm_kernel(float* __restrict__ attn) {
    size_t i = (size_t)blockIdx.x * blockDim.x + threadIdx.x; // index in float4 units
    size_t total4 = ATT_E / 4;
    if (i >= total4) return;
    size_t row = i / (SS / 4);
    float inv = g_rinv[row];
    float4 v = ((float4*)attn)[i];
    v.x *= inv; v.y *= inv; v.z *= inv; v.w *= inv;
    ((float4*)attn)[i] = v;
}

// ---------------- final output GEMM: out = pre @ Wo ----------------
// grid: (ROWS/64, DM/64), block 256
__global__ __launch_bounds__(256) void outgemm_kernel(const float* __restrict__ Wo,
                                                      float* __restrict__ out) {
    const int m0 = blockIdx.x * 64;
    const int n0 = blockIdx.y * 64;
    __shared__ float AsT[16][68];
    __shared__ float Bs[16][68];
    const int tid = threadIdx.x;
    const int tx = tid & 15, ty = tid >> 4;
    float acc[4][4] = {};

    for (int k0 = 0; k0 < DM; k0 += 16) {
        int e = tid * 4;
        {
            int m = e >> 4, kk = e & 15;
            float4 a = *(const float4*)(g_pre + (size_t)(m0 + m) * DM + k0 + kk);
            AsT[kk + 0][m] = a.x; AsT[kk + 1][m] = a.y;
            AsT[kk + 2][m] = a.z; AsT[kk + 3][m] = a.w;
        }
        {
            int kk = e >> 6, nn = e & 63;
            float4 w4 = *(const float4*)(Wo + (size_t)(k0 + kk) * DM + n0 + nn);
            *(float4*)&Bs[kk][nn] = w4;
        }
        __syncthreads();
#pragma unroll
        for (int kk = 0; kk < 16; kk++) {
            float4 av = *(const float4*)&AsT[kk][ty * 4];
            float4 bv = *(const float4*)&Bs[kk][tx * 4];
            fma4x4(acc, av, bv);
        }
        __syncthreads();
    }
#pragma unroll
    for (int i = 0; i < 4; i++) {
        float4 o = make_float4(acc[i][0], acc[i][1], acc[i][2], acc[i][3]);
        *(float4*)(out + (size_t)(m0 + ty * 4 + i) * DM + n0 + tx * 4) = o;
    }
}

// ---------------- launch ----------------
extern "C" void kernel_launch(void* const* d_in, const int* in_sizes, int n_in,
                              void* d_out, int out_size) {
    const float* Q   = (const float*)d_in[0];
    const float* K   = (const float*)d_in[1];
    const float* V   = (const float*)d_in[2];
    const float* Wq  = (const float*)d_in[3];
    const float* Wk  = (const float*)d_in[4];
    const float* Wv  = (const float*)d_in[5];
    const float* Wo  = (const float*)d_in[6];
    const void*  msk = d_in[7];

    float* out = (float*)d_out;
    float* attn = nullptr;
    if ((size_t)out_size >= (size_t)OUT_E + ATT_E) attn = out + OUT_E;

    float *qp, *kp, *vp;
    cudaGetSymbolAddress((void**)&qp, g_q);
    cudaGetSymbolAddress((void**)&kp, g_k);
    cudaGetSymbolAddress((void**)&vp, g_v);

    const int ATTN_SMEM = (3 * 64 * 68 + 64 * 65) * 4 + 64 * 4; // 69120 B
    cudaFuncSetAttribute(attn_kernel, cudaFuncAttributeMaxDynamicSharedMemorySize, ATTN_SMEM);

    mask_kernel<<<1, 256>>>(msk, ROWS);

    dim3 pg(ROWS / 64, NH);
    proj_kernel<<<pg, 256>>>(Q, Wq, qp);
    proj_kernel<<<pg, 256>>>(K, Wk, kp);
    proj_kernel<<<pg, 256>>>(V, Wv, vp);

    dim3 ag(SS / 64, BB, NH);
    attn_kernel<<<ag, 256, ATTN_SMEM>>>(attn);

    if (attn) {
        int nblk = (int)(ATT_E / 4 / 256);
        norm_kernel<<<nblk, 256>>>(attn);
    }

    dim3 og(ROWS / 64, DM / 64);
    outgemm_kernel<<<og, 256>>>(Wo, out);
}

// round 11
// speedup vs baseline: 1.4660x; 1.4660x over previous
#include <cuda_runtime.h>
#include <cuda_bf16.h>
#include <cstdint>
#include <cstddef>

#define NH 16
#define DK 64
#define DV 64
#define DM 1024
#define BB 2
#define SS 2048

#define HB   (NH * BB)            // 32
#define ROWS (BB * SS)            // 4096
#define OUT_E (ROWS * DM)         // 4,194,304 floats
#define ATT_E ((size_t)HB * SS * SS) // 134,217,728 floats

// ---------------- scratch (no allocations allowed) ----------------
__device__ float g_q[HB * SS * DK];        // q[hb][s][k]
__device__ float g_k[HB * SS * DK];
__device__ float g_v[HB * SS * DV];        // v[hb][s][dv]
__device__ float g_pre[ROWS * NH * DV];    // pre[b][s][h*64+dv]
__device__ float g_rinv[HB * SS];
__device__ int   g_mask[ROWS];

// ================= portable PTX helpers (sm_80+ ISA, no arch-variant features) ==========
__device__ __forceinline__ uint32_t smem_u32(const void* p) {
    uint32_t a;
    asm("{ .reg .u64 t; cvta.to.shared.u64 t, %1; cvt.u32.u64 %0, t; }" : "=r"(a) : "l"(p));
    return a;
}
__device__ __forceinline__ void ldm_x4(uint32_t (&r)[4], uint32_t addr) {
    asm volatile("ldmatrix.sync.aligned.m8n8.x4.shared.b16 {%0,%1,%2,%3}, [%4];"
        : "=r"(r[0]), "=r"(r[1]), "=r"(r[2]), "=r"(r[3]) : "r"(addr));
}
__device__ __forceinline__ void ldm_x2(uint32_t (&r)[2], uint32_t addr) {
    asm volatile("ldmatrix.sync.aligned.m8n8.x2.shared.b16 {%0,%1}, [%2];"
        : "=r"(r[0]), "=r"(r[1]) : "r"(addr));
}
__device__ __forceinline__ void ldm_x2_trans(uint32_t (&r)[2], uint32_t addr) {
    asm volatile("ldmatrix.sync.aligned.m8n8.x2.trans.shared.b16 {%0,%1}, [%2];"
        : "=r"(r[0]), "=r"(r[1]) : "r"(addr));
}
// D(16x8,f32) += A(16x16,bf16) * B(16x8,bf16)
__device__ __forceinline__ void mma16816(float (&d)[4], const uint32_t (&a)[4], const uint32_t (&b)[2]) {
    asm volatile("mma.sync.aligned.m16n8k16.row.col.f32.bf16.bf16.f32 "
        "{%0,%1,%2,%3}, {%4,%5,%6,%7}, {%8,%9}, {%0,%1,%2,%3};"
        : "+f"(d[0]), "+f"(d[1]), "+f"(d[2]), "+f"(d[3])
        : "r"(a[0]), "r"(a[1]), "r"(a[2]), "r"(a[3]), "r"(b[0]), "r"(b[1]));
}
__device__ __forceinline__ uint32_t bf2_bits(__nv_bfloat162 v) {
    return *reinterpret_cast<uint32_t*>(&v);
}

// ---------------- mask conversion (dtype-robust) ----------------
__global__ void mask_kernel(const void* mraw, int n) {
    __shared__ int mode;
    if (threadIdx.x == 0) {
        const unsigned* mi = (const unsigned*)mraw;
        const float* mf = (const float*)mraw;
        int lim = n / 4; if (lim > 1024) lim = 1024;
        int ok_i = 1, ok_f = 1;
        for (int i = 0; i < lim; i++) {
            if (mi[i] > 1u) ok_i = 0;
            float f = mf[i];
            if (!(f == 0.0f || f == 1.0f)) ok_f = 0;
            if (!ok_i && !ok_f) break;
        }
        mode = ok_i ? 1 : (ok_f ? 2 : 0);
    }
    __syncthreads();
    int md = mode;
    for (int i = threadIdx.x; i < n; i += blockDim.x) {
        int val;
        if (md == 1)      val = ((const int*)mraw)[i] != 0;
        else if (md == 2) val = ((const float*)mraw)[i] != 0.0f;
        else              val = ((const unsigned char*)mraw)[i] != 0;
        g_mask[i] = val;
    }
}

__device__ __forceinline__ void fma4x4(float (&acc)[4][4], const float4 av, const float4 bv) {
    acc[0][0] += av.x * bv.x; acc[0][1] += av.x * bv.y; acc[0][2] += av.x * bv.z; acc[0][3] += av.x * bv.w;
    acc[1][0] += av.y * bv.x; acc[1][1] += av.y * bv.y; acc[1][2] += av.y * bv.z; acc[1][3] += av.y * bv.w;
    acc[2][0] += av.z * bv.x; acc[2][1] += av.z * bv.y; acc[2][2] += av.z * bv.z; acc[2][3] += av.z * bv.w;
    acc[3][0] += av.w * bv.x; acc[3][1] += av.w * bv.y; acc[3][2] += av.w * bv.z; acc[3][3] += av.w * bv.w;
}

// ---------------- per-head projection GEMM (f32 FFMA, round-2 proven) ----------------
__global__ __launch_bounds__(256) void proj_kernel(const float* __restrict__ X,
                                                   const float* __restrict__ W,
                                                   float* __restrict__ C) {
    const int h = blockIdx.y;
    const int m0 = blockIdx.x * 64;
    __shared__ float AsT[16][68];
    __shared__ float Ws[16][68];
    const int tid = threadIdx.x;
    const int tx = tid & 15, ty = tid >> 4;
    float acc[4][4] = {};
    const float* Wh = W + (size_t)h * DM * DK;

    for (int k0 = 0; k0 < DM; k0 += 16) {
        int e = tid * 4;
        {
            int m = e >> 4, kk = e & 15;
            float4 a = *(const float4*)(X + (size_t)(m0 + m) * DM + k0 + kk);
            AsT[kk + 0][m] = a.x; AsT[kk + 1][m] = a.y;
            AsT[kk + 2][m] = a.z; AsT[kk + 3][m] = a.w;
        }
        {
            int kk = e >> 6, nn = e & 63;
            float4 w4 = *(const float4*)(Wh + (size_t)(k0 + kk) * DK + nn);
            *(float4*)&Ws[kk][nn] = w4;
        }
        __syncthreads();
#pragma unroll
        for (int kk = 0; kk < 16; kk++) {
            float4 av = *(const float4*)&AsT[kk][ty * 4];
            float4 bv = *(const float4*)&Ws[kk][tx * 4];
            fma4x4(acc, av, bv);
        }
        __syncthreads();
    }
    const int b = m0 / SS;
    const int s0 = m0 - b * SS;
    const size_t rbase = (size_t)(h * BB + b) * SS + s0;
#pragma unroll
    for (int i = 0; i < 4; i++) {
        float4 o = make_float4(acc[i][0], acc[i][1], acc[i][2], acc[i][3]);
        *(float4*)(C + (rbase + ty * 4 + i) * DK + tx * 4) = o;
    }
}

// ---------------- mma.sync attention ----------------
// smem layout (bytes), bf16 tiles 64 x 72 (144B row stride, 16B-aligned)
#define ROW_B 144
#define SM_QH 0
#define SM_QL 9216
#define SM_KH 18432
#define SM_KL 27648
#define SM_VH 36864
#define SM_VL 46080
#define SM_MSK 55296
#define SM_ROWSUM 55552
#define SM_INV 56064
#define ATTN_SMEM 56320

// f32 64x64 tile -> bf16 hi/lo smem tiles
__device__ __forceinline__ void load_cvt_tile(const float* __restrict__ gsrc,
                                              char* sh, char* sl, int tid) {
#pragma unroll
    for (int it = 0; it < 4; it++) {
        int i = tid + it * 256;          // float4 index, 1024 total
        int row = i >> 4;
        int c4 = (i & 15) * 4;
        float4 f = *(const float4*)(gsrc + row * 64 + c4);
        __nv_bfloat162 h0 = __floats2bfloat162_rn(f.x, f.y);
        __nv_bfloat162 h1 = __floats2bfloat162_rn(f.z, f.w);
        __nv_bfloat162 l0 = __floats2bfloat162_rn(f.x - __low2float(h0), f.y - __high2float(h0));
        __nv_bfloat162 l1 = __floats2bfloat162_rn(f.z - __low2float(h1), f.w - __high2float(h1));
        *(uint2*)(sh + row * ROW_B + c4 * 2) = make_uint2(bf2_bits(h0), bf2_bits(h1));
        *(uint2*)(sl + row * ROW_B + c4 * 2) = make_uint2(bf2_bits(l0), bf2_bits(l1));
    }
}

// grid (SS/64, BB, NH), 256 threads (8 warps: mw = wid&3 m16-block, nw = wid>>2 key-half)
__global__ void __launch_bounds__(256) attn_mma_kernel(float* __restrict__ attn) {
    extern __shared__ char sm[];
    uint32_t sb = smem_u32(sm);
    const int tid = threadIdx.x, lane = tid & 31, wid = tid >> 5;
    const int mw = wid & 3, nw = wid >> 2;
    const int h = blockIdx.z, b = blockIdx.y;
    const int q0 = blockIdx.x * 64;
    const int hb = h * BB + b;

    load_cvt_tile(g_q + ((size_t)hb * SS + q0) * DK, sm + SM_QH, sm + SM_QL, tid);
    __syncthreads();

    // Q fragments (held in registers for whole kernel)
    uint32_t qh[4][4], ql[4][4];
    {
        uint32_t roff = (uint32_t)(mw * 16 + (lane & 15)) * ROW_B + (uint32_t)(lane >> 4) * 16;
#pragma unroll
        for (int ks = 0; ks < 4; ks++) {
            ldm_x4(qh[ks], sb + SM_QH + roff + ks * 32);
            ldm_x4(ql[ks], sb + SM_QL + roff + ks * 32);
        }
    }

    float oacc[8][4] = {};
    float rs0 = 0.0f, rs1 = 0.0f;
    const int g = lane >> 2, qq = (lane & 3) * 2;
    const int r0 = mw * 16 + g, r1 = r0 + 8;
    float* arow0 = attn ? attn + ((size_t)hb * SS + q0 + r0) * SS : (float*)0;
    float* arow1 = attn ? attn + ((size_t)hb * SS + q0 + r1) * SS : (float*)0;

    for (int kt = 0; kt < SS; kt += 64) {
        load_cvt_tile(g_k + ((size_t)hb * SS + kt) * DK, sm + SM_KH, sm + SM_KL, tid);
        load_cvt_tile(g_v + ((size_t)hb * SS + kt) * DV, sm + SM_VH, sm + SM_VL, tid);
        if (tid < 64) ((int*)(sm + SM_MSK))[tid] = g_mask[b * SS + kt + tid];
        __syncthreads();

        // ---- scores S = Q K^T (3-pass bf16 split) ----
        float sacc[4][4] = {};
        {
            const int l16 = lane & 15;
            uint32_t rbase = (uint32_t)(nw * 32 + (l16 & 7)) * ROW_B + (uint32_t)((l16 >> 3) & 1) * 16;
#pragma unroll
            for (int nt = 0; nt < 4; nt++) {
                uint32_t ro = rbase + (uint32_t)nt * (8 * ROW_B);
#pragma unroll
                for (int ks = 0; ks < 4; ks++) {
                    uint32_t co = ro + ks * 32;
                    uint32_t bh[2], bl[2];
                    ldm_x2(bh, sb + SM_KH + co);
                    ldm_x2(bl, sb + SM_KL + co);
                    mma16816(sacc[nt], qh[ks], bh);
                    mma16816(sacc[nt], ql[ks], bh);
                    mma16816(sacc[nt], qh[ks], bl);
                }
            }
        }

        // ---- epilogue: mask + exp + attn store + rowsum + P->bf16 hi/lo a-frags ----
        uint32_t ph[4][2], pl[4][2];
        {
            const int* msk = (const int*)(sm + SM_MSK);
#pragma unroll
            for (int nt = 0; nt < 4; nt++) {
                int cb = nw * 32 + nt * 8 + qq;
                int m0 = msk[cb], m1 = msk[cb + 1];
                float e00 = m0 ? __expf(sacc[nt][0] * 0.125f) : 0.0f;
                float e01 = m1 ? __expf(sacc[nt][1] * 0.125f) : 0.0f;
                float e10 = m0 ? __expf(sacc[nt][2] * 0.125f) : 0.0f;
                float e11 = m1 ? __expf(sacc[nt][3] * 0.125f) : 0.0f;
                rs0 += e00 + e01; rs1 += e10 + e11;
                if (arow0) {
                    *(float2*)(arow0 + kt + cb) = make_float2(e00, e01);
                    *(float2*)(arow1 + kt + cb) = make_float2(e10, e11);
                }
                __nv_bfloat162 h0 = __floats2bfloat162_rn(e00, e01);
                __nv_bfloat162 h1 = __floats2bfloat162_rn(e10, e11);
                __nv_bfloat162 l0 = __floats2bfloat162_rn(e00 - __low2float(h0), e01 - __high2float(h0));
                __nv_bfloat162 l1 = __floats2bfloat162_rn(e10 - __low2float(h1), e11 - __high2float(h1));
                ph[nt][0] = bf2_bits(h0); ph[nt][1] = bf2_bits(h1);
                pl[nt][0] = bf2_bits(l0); pl[nt][1] = bf2_bits(l1);
            }
        }

        // ---- PV: O += P V (this warp's 32 keys; 3-pass) ----
        {
            const int l16 = lane & 15;
#pragma unroll
            for (int ks = 0; ks < 2; ks++) {
                uint32_t ah[4] = {ph[2*ks][0], ph[2*ks][1], ph[2*ks+1][0], ph[2*ks+1][1]};
                uint32_t al[4] = {pl[2*ks][0], pl[2*ks][1], pl[2*ks+1][0], pl[2*ks+1][1]};
                uint32_t roff = (uint32_t)(nw * 32 + ks * 16 + l16) * ROW_B;
#pragma unroll
                for (int vt = 0; vt < 8; vt++) {
                    uint32_t co = roff + vt * 16;
                    uint32_t bh[2], bl[2];
                    ldm_x2_trans(bh, sb + SM_VH + co);
                    ldm_x2_trans(bl, sb + SM_VL + co);
                    mma16816(oacc[vt], ah, bh);
                    mma16816(oacc[vt], al, bh);
                    mma16816(oacc[vt], ah, bl);
                }
            }
        }
        __syncthreads();
    }

    // ---- row-sum reduction (quad shfl, then cross key-half via smem) ----
    rs0 += __shfl_xor_sync(0xffffffffu, rs0, 1);
    rs0 += __shfl_xor_sync(0xffffffffu, rs0, 2);
    rs1 += __shfl_xor_sync(0xffffffffu, rs1, 1);
    rs1 += __shfl_xor_sync(0xffffffffu, rs1, 2);
    float* rowsum = (float*)(sm + SM_ROWSUM);
    if ((lane & 3) == 0) {
        rowsum[nw * 64 + r0] = rs0;
        rowsum[nw * 64 + r1] = rs1;
    }
    // nw==1 warps publish their O partial (reuse K smem region)
    float* osh = (float*)(sm + SM_KH);
    if (nw == 1) {
#pragma unroll
        for (int vt = 0; vt < 8; vt++) {
            int c = vt * 8 + qq;
            *(float2*)(osh + r0 * 64 + c) = make_float2(oacc[vt][0], oacc[vt][1]);
            *(float2*)(osh + r1 * 64 + c) = make_float2(oacc[vt][2], oacc[vt][3]);
        }
    }
    __syncthreads();
    float* invrow = (float*)(sm + SM_INV);
    if (tid < 64) {
        float t = rowsum[tid] + rowsum[64 + tid];
        float iv = (t > 0.0f) ? (1.0f / t) : 0.0f;
        invrow[tid] = iv;
        g_rinv[(size_t)hb * SS + q0 + tid] = iv;
    }
    __syncthreads();
    if (nw == 0) {
        float iv0 = invrow[r0], iv1 = invrow[r1];
        float* p0 = g_pre + ((size_t)(b * SS + q0 + r0)) * (NH * DV) + h * DV;
        float* p1 = g_pre + ((size_t)(b * SS + q0 + r1)) * (NH * DV) + h * DV;
#pragma unroll
        for (int vt = 0; vt < 8; vt++) {
            int c = vt * 8 + qq;
            float2 t0 = *(float2*)(osh + r0 * 64 + c);
            float2 t1 = *(float2*)(osh + r1 * 64 + c);
            *(float2*)(p0 + c) = make_float2((oacc[vt][0] + t0.x) * iv0, (oacc[vt][1] + t0.y) * iv0);
            *(float2*)(p1 + c) = make_float2((oacc[vt][2] + t1.x) * iv1, (oacc[vt][3] + t1.y) * iv1);
        }
    }
}

// ---------------- attn normalization pass ----------------
__global__ __launch_bounds__(256) void norm_kernel(float* __restrict__ attn) {
    size_t i = (size_t)blockIdx.x * blockDim.x + threadIdx.x;
    size_t total4 = ATT_E / 4;
    if (i >= total4) return;
    size_t row = i / (SS / 4);
    float inv = g_rinv[row];
    float4 v = ((float4*)attn)[i];
    v.x *= inv; v.y *= inv; v.z *= inv; v.w *= inv;
    ((float4*)attn)[i] = v;
}

// ---------------- final output GEMM: out = pre @ Wo ----------------
__global__ __launch_bounds__(256) void outgemm_kernel(const float* __restrict__ Wo,
                                                      float* __restrict__ out) {
    const int m0 = blockIdx.x * 64;
    const int n0 = blockIdx.y * 64;
    __shared__ float AsT[16][68];
    __shared__ float Bs[16][68];
    const int tid = threadIdx.x;
    const int tx = tid & 15, ty = tid >> 4;
    float acc[4][4] = {};

    for (int k0 = 0; k0 < DM; k0 += 16) {
        int e = tid * 4;
        {
            int m = e >> 4, kk = e & 15;
            float4 a = *(const float4*)(g_pre + (size_t)(m0 + m) * DM + k0 + kk);
            AsT[kk + 0][m] = a.x; AsT[kk + 1][m] = a.y;
            AsT[kk + 2][m] = a.z; AsT[kk + 3][m] = a.w;
        }
        {
            int kk = e >> 6, nn = e & 63;
            float4 w4 = *(const float4*)(Wo + (size_t)(k0 + kk) * DM + n0 + nn);
            *(float4*)&Bs[kk][nn] = w4;
        }
        __syncthreads();
#pragma unroll
        for (int kk = 0; kk < 16; kk++) {
            float4 av = *(const float4*)&AsT[kk][ty * 4];
            float4 bv = *(const float4*)&Bs[kk][tx * 4];
            fma4x4(acc, av, bv);
        }
        __syncthreads();
    }
#pragma unroll
    for (int i = 0; i < 4; i++) {
        float4 o = make_float4(acc[i][0], acc[i][1], acc[i][2], acc[i][3]);
        *(float4*)(out + (size_t)(m0 + ty * 4 + i) * DM + n0 + tx * 4) = o;
    }
}

// ---------------- launch ----------------
extern "C" void kernel_launch(void* const* d_in, const int* in_sizes, int n_in,
                              void* d_out, int out_size) {
    const float* Q   = (const float*)d_in[0];
    const float* K   = (const float*)d_in[1];
    const float* V   = (const float*)d_in[2];
    const float* Wq  = (const float*)d_in[3];
    const float* Wk  = (const float*)d_in[4];
    const float* Wv  = (const float*)d_in[5];
    const float* Wo  = (const float*)d_in[6];
    const void*  msk = d_in[7];

    float* out = (float*)d_out;
    float* attn = nullptr;
    if ((size_t)out_size >= (size_t)OUT_E + ATT_E) attn = out + OUT_E;

    float *qp, *kp, *vp;
    cudaGetSymbolAddress((void**)&qp, g_q);
    cudaGetSymbolAddress((void**)&kp, g_k);
    cudaGetSymbolAddress((void**)&vp, g_v);

    cudaFuncSetAttribute(attn_mma_kernel, cudaFuncAttributeMaxDynamicSharedMemorySize, ATTN_SMEM);

    mask_kernel<<<1, 256>>>(msk, ROWS);

    dim3 pg(ROWS / 64, NH);
    proj_kernel<<<pg, 256>>>(Q, Wq, qp);
    proj_kernel<<<pg, 256>>>(K, Wk, kp);
    proj_kernel<<<pg, 256>>>(V, Wv, vp);

    dim3 ag(SS / 64, BB, NH);
    attn_mma_kernel<<<ag, 256, ATTN_SMEM>>>(attn);

    if (attn) {
        int nblk = (int)(ATT_E / 4 / 256);
        norm_kernel<<<nblk, 256>>>(attn);
    }

    dim3 og(ROWS / 64, DM / 64);
    outgemm_kernel<<<og, 256>>>(Wo, out);
}

// round 13
// speedup vs baseline: 2.2597x; 1.5414x over previous
#include <cuda_runtime.h>
#include <cuda_bf16.h>
#include <cstdint>
#include <cstddef>

#define NH 16
#define DK 64
#define DV 64
#define DM 1024
#define BB 2
#define SS 2048

#define HB   (NH * BB)            // 32
#define ROWS (BB * SS)            // 4096
#define OUT_E (ROWS * DM)         // 4,194,304 floats
#define ATT_E ((size_t)HB * SS * SS) // 134,217,728 floats

// ---------------- scratch (no allocations allowed) ----------------
__device__ float g_q[HB * SS * DK];        // q[hb][s][k]
__device__ float g_k[HB * SS * DK];
__device__ float g_v[HB * SS * DV];        // v[hb][s][dv]
__device__ float g_pre[ROWS * NH * DV];    // pre[b][s][h*64+dv]
__device__ float g_rinv[HB * SS];
__device__ int   g_mask[ROWS];
// bf16 hi/lo operands for mma GEMMs
__device__ __nv_bfloat16 g_xh[3][ROWS * DM];        // Q,K,V inputs
__device__ __nv_bfloat16 g_xl[3][ROWS * DM];
__device__ __nv_bfloat16 g_wph[3][NH * DM * DK];    // Wq,Wk,Wv
__device__ __nv_bfloat16 g_wpl[3][NH * DM * DK];
__device__ __nv_bfloat16 g_woh[DM * DM];
__device__ __nv_bfloat16 g_wol[DM * DM];
__device__ __nv_bfloat16 g_preh[ROWS * NH * DV];
__device__ __nv_bfloat16 g_prel[ROWS * NH * DV];

// ================= portable PTX helpers (sm_80+ ISA) ==========
__device__ __forceinline__ uint32_t smem_u32(const void* p) {
    uint32_t a;
    asm("{ .reg .u64 t; cvta.to.shared.u64 t, %1; cvt.u32.u64 %0, t; }" : "=r"(a) : "l"(p));
    return a;
}
__device__ __forceinline__ void ldm_x4(uint32_t (&r)[4], uint32_t addr) {
    asm volatile("ldmatrix.sync.aligned.m8n8.x4.shared.b16 {%0,%1,%2,%3}, [%4];"
        : "=r"(r[0]), "=r"(r[1]), "=r"(r[2]), "=r"(r[3]) : "r"(addr));
}
__device__ __forceinline__ void ldm_x2(uint32_t (&r)[2], uint32_t addr) {
    asm volatile("ldmatrix.sync.aligned.m8n8.x2.shared.b16 {%0,%1}, [%2];"
        : "=r"(r[0]), "=r"(r[1]) : "r"(addr));
}
__device__ __forceinline__ void ldm_x2_trans(uint32_t (&r)[2], uint32_t addr) {
    asm volatile("ldmatrix.sync.aligned.m8n8.x2.trans.shared.b16 {%0,%1}, [%2];"
        : "=r"(r[0]), "=r"(r[1]) : "r"(addr));
}
__device__ __forceinline__ void mma16816(float (&d)[4], const uint32_t (&a)[4], const uint32_t (&b)[2]) {
    asm volatile("mma.sync.aligned.m16n8k16.row.col.f32.bf16.bf16.f32 "
        "{%0,%1,%2,%3}, {%4,%5,%6,%7}, {%8,%9}, {%0,%1,%2,%3};"
        : "+f"(d[0]), "+f"(d[1]), "+f"(d[2]), "+f"(d[3])
        : "r"(a[0]), "r"(a[1]), "r"(a[2]), "r"(a[3]), "r"(b[0]), "r"(b[1]));
}
__device__ __forceinline__ uint32_t bf2_bits(__nv_bfloat162 v) {
    return *reinterpret_cast<uint32_t*>(&v);
}

// ---------------- mask conversion (dtype-robust) ----------------
__global__ void mask_kernel(const void* mraw, int n) {
    __shared__ int mode;
    if (threadIdx.x == 0) {
        const unsigned* mi = (const unsigned*)mraw;
        const float* mf = (const float*)mraw;
        int lim = n / 4; if (lim > 1024) lim = 1024;
        int ok_i = 1, ok_f = 1;
        for (int i = 0; i < lim; i++) {
            if (mi[i] > 1u) ok_i = 0;
            float f = mf[i];
            if (!(f == 0.0f || f == 1.0f)) ok_f = 0;
            if (!ok_i && !ok_f) break;
        }
        mode = ok_i ? 1 : (ok_f ? 2 : 0);
    }
    __syncthreads();
    int md = mode;
    for (int i = threadIdx.x; i < n; i += blockDim.x) {
        int val;
        if (md == 1)      val = ((const int*)mraw)[i] != 0;
        else if (md == 2) val = ((const float*)mraw)[i] != 0.0f;
        else              val = ((const unsigned char*)mraw)[i] != 0;
        g_mask[i] = val;
    }
}

// ---------------- fp32 -> bf16 hi/lo conversion (grid-stride over float4) ----------------
__global__ __launch_bounds__(256) void cvt_kernel(const float* __restrict__ in,
                                                  __nv_bfloat16* __restrict__ oh,
                                                  __nv_bfloat16* __restrict__ ol, int n4) {
    int i = blockIdx.x * blockDim.x + threadIdx.x;
    if (i >= n4) return;
    float4 f = ((const float4*)in)[i];
    __nv_bfloat162 h0 = __floats2bfloat162_rn(f.x, f.y);
    __nv_bfloat162 h1 = __floats2bfloat162_rn(f.z, f.w);
    __nv_bfloat162 l0 = __floats2bfloat162_rn(f.x - __low2float(h0), f.y - __high2float(h0));
    __nv_bfloat162 l1 = __floats2bfloat162_rn(f.z - __low2float(h1), f.w - __high2float(h1));
    ((uint2*)oh)[i] = make_uint2(bf2_bits(h0), bf2_bits(h1));
    ((uint2*)ol)[i] = make_uint2(bf2_bits(l0), bf2_bits(l1));
}

// ---------------- mma GEMM tiles: 64x64 C, K-loop, 8 warps (4 m-blocks x 2 n-halves) ------
#define ROW_B 144
#define SXH 0
#define SXL 9216
#define SWH 18432
#define SWL 27648

// per-head projection: C[((h*BB+b)*SS+s)][n] = X[m][:] @ W[h][:][n]
__global__ void __launch_bounds__(256) proj_mma_kernel(const __nv_bfloat16* __restrict__ Xh,
                                                       const __nv_bfloat16* __restrict__ Xl,
                                                       const __nv_bfloat16* __restrict__ Wh,
                                                       const __nv_bfloat16* __restrict__ Wl,
                                                       float* __restrict__ C) {
    __shared__ char sm[4 * 64 * ROW_B];
    uint32_t sb = smem_u32(sm);
    const int tid = threadIdx.x, lane = tid & 31, wid = tid >> 5;
    const int mw = wid & 3, nw = wid >> 2;
    const int h = blockIdx.y;
    const int m0 = blockIdx.x * 64;
    const char* xh_g = (const char*)(Xh + (size_t)m0 * DM);
    const char* xl_g = (const char*)(Xl + (size_t)m0 * DM);
    const char* wh_g = (const char*)(Wh + (size_t)h * DM * DK);
    const char* wl_g = (const char*)(Wl + (size_t)h * DM * DK);

    float acc[4][4] = {};
    for (int k0 = 0; k0 < DM; k0 += 64) {
#pragma unroll
        for (int it = 0; it < 2; it++) {
            int i = tid + it * 256;
            int r = i >> 3, ch = (i & 7) * 16;
            size_t xo = (size_t)r * (DM * 2) + (size_t)k0 * 2 + ch;
            size_t wo = (size_t)(k0 + r) * (DK * 2) + ch;
            *(uint4*)(sm + SXH + r * ROW_B + ch) = *(const uint4*)(xh_g + xo);
            *(uint4*)(sm + SXL + r * ROW_B + ch) = *(const uint4*)(xl_g + xo);
            *(uint4*)(sm + SWH + r * ROW_B + ch) = *(const uint4*)(wh_g + wo);
            *(uint4*)(sm + SWL + r * ROW_B + ch) = *(const uint4*)(wl_g + wo);
        }
        __syncthreads();
        const int l16 = lane & 15;
#pragma unroll
        for (int ks = 0; ks < 4; ks++) {
            uint32_t ah[4], al[4];
            uint32_t aoff = (uint32_t)(mw * 16 + l16) * ROW_B + (uint32_t)(lane >> 4) * 16 + ks * 32;
            ldm_x4(ah, sb + SXH + aoff);
            ldm_x4(al, sb + SXL + aoff);
            uint32_t broff = (uint32_t)(ks * 16 + l16) * ROW_B;
#pragma unroll
            for (int nt = 0; nt < 4; nt++) {
                uint32_t co = broff + (uint32_t)(nw * 32 + nt * 8) * 2;
                uint32_t bh[2], bl[2];
                ldm_x2_trans(bh, sb + SWH + co);
                ldm_x2_trans(bl, sb + SWL + co);
                mma16816(acc[nt], ah, bh);
                mma16816(acc[nt], al, bh);
                mma16816(acc[nt], ah, bl);
            }
        }
        __syncthreads();
    }
    const int b = m0 / SS;
    const int s0 = m0 - b * SS;
    const int hb = h * BB + b;
    const int g = lane >> 2, qq = (lane & 3) * 2;
    float* c0 = C + ((size_t)hb * SS + s0 + mw * 16 + g) * DK;
    float* c1 = c0 + 8 * DK;
#pragma unroll
    for (int nt = 0; nt < 4; nt++) {
        int c = nw * 32 + nt * 8 + qq;
        *(float2*)(c0 + c) = make_float2(acc[nt][0], acc[nt][1]);
        *(float2*)(c1 + c) = make_float2(acc[nt][2], acc[nt][3]);
    }
}

// out[m][n0+n] = pre[m][:] @ Wo[:][n0+n]
__global__ void __launch_bounds__(256) outgemm_mma_kernel(float* __restrict__ out) {
    __shared__ char sm[4 * 64 * ROW_B];
    uint32_t sb = smem_u32(sm);
    const int tid = threadIdx.x, lane = tid & 31, wid = tid >> 5;
    const int mw = wid & 3, nw = wid >> 2;
    const int m0 = blockIdx.x * 64;
    const int n0 = blockIdx.y * 64;
    const char* ah_g = (const char*)(g_preh + (size_t)m0 * DM);
    const char* al_g = (const char*)(g_prel + (size_t)m0 * DM);
    const char* bh_g = (const char*)g_woh;
    const char* bl_g = (const char*)g_wol;

    float acc[4][4] = {};
    for (int k0 = 0; k0 < DM; k0 += 64) {
#pragma unroll
        for (int it = 0; it < 2; it++) {
            int i = tid + it * 256;
            int r = i >> 3, ch = (i & 7) * 16;
            size_t ao = (size_t)r * (DM * 2) + (size_t)k0 * 2 + ch;
            size_t bo = (size_t)(k0 + r) * (DM * 2) + (size_t)n0 * 2 + ch;
            *(uint4*)(sm + SXH + r * ROW_B + ch) = *(const uint4*)(ah_g + ao);
            *(uint4*)(sm + SXL + r * ROW_B + ch) = *(const uint4*)(al_g + ao);
            *(uint4*)(sm + SWH + r * ROW_B + ch) = *(const uint4*)(bh_g + bo);
            *(uint4*)(sm + SWL + r * ROW_B + ch) = *(const uint4*)(bl_g + bo);
        }
        __syncthreads();
        const int l16 = lane & 15;
#pragma unroll
        for (int ks = 0; ks < 4; ks++) {
            uint32_t ah[4], al[4];
            uint32_t aoff = (uint32_t)(mw * 16 + l16) * ROW_B + (uint32_t)(lane >> 4) * 16 + ks * 32;
            ldm_x4(ah, sb + SXH + aoff);
            ldm_x4(al, sb + SXL + aoff);
            uint32_t broff = (uint32_t)(ks * 16 + l16) * ROW_B;
#pragma unroll
            for (int nt = 0; nt < 4; nt++) {
                uint32_t co = broff + (uint32_t)(nw * 32 + nt * 8) * 2;
                uint32_t bh[2], bl[2];
                ldm_x2_trans(bh, sb + SWH + co);
                ldm_x2_trans(bl, sb + SWL + co);
                mma16816(acc[nt], ah, bh);
                mma16816(acc[nt], al, bh);
                mma16816(acc[nt], ah, bl);
            }
        }
        __syncthreads();
    }
    const int g = lane >> 2, qq = (lane & 3) * 2;
    float* c0 = out + (size_t)(m0 + mw * 16 + g) * DM + n0;
    float* c1 = c0 + 8 * DM;
#pragma unroll
    for (int nt = 0; nt < 4; nt++) {
        int c = nw * 32 + nt * 8 + qq;
        *(float2*)(c0 + c) = make_float2(acc[nt][0], acc[nt][1]);
        *(float2*)(c1 + c) = make_float2(acc[nt][2], acc[nt][3]);
    }
}

// ---------------- mma.sync attention (round-11 proven, unchanged) ----------------
#define SM_QH 0
#define SM_QL 9216
#define SM_KH 18432
#define SM_KL 27648
#define SM_VH 36864
#define SM_VL 46080
#define SM_MSK 55296
#define SM_ROWSUM 55552
#define SM_INV 56064
#define ATTN_SMEM 56320

__device__ __forceinline__ void load_cvt_tile(const float* __restrict__ gsrc,
                                              char* sh, char* sl, int tid) {
#pragma unroll
    for (int it = 0; it < 4; it++) {
        int i = tid + it * 256;
        int row = i >> 4;
        int c4 = (i & 15) * 4;
        float4 f = *(const float4*)(gsrc + row * 64 + c4);
        __nv_bfloat162 h0 = __floats2bfloat162_rn(f.x, f.y);
        __nv_bfloat162 h1 = __floats2bfloat162_rn(f.z, f.w);
        __nv_bfloat162 l0 = __floats2bfloat162_rn(f.x - __low2float(h0), f.y - __high2float(h0));
        __nv_bfloat162 l1 = __floats2bfloat162_rn(f.z - __low2float(h1), f.w - __high2float(h1));
        *(uint2*)(sh + row * ROW_B + c4 * 2) = make_uint2(bf2_bits(h0), bf2_bits(h1));
        *(uint2*)(sl + row * ROW_B + c4 * 2) = make_uint2(bf2_bits(l0), bf2_bits(l1));
    }
}

__global__ void __launch_bounds__(256) attn_mma_kernel(float* __restrict__ attn) {
    extern __shared__ char sm[];
    uint32_t sb = smem_u32(sm);
    const int tid = threadIdx.x, lane = tid & 31, wid = tid >> 5;
    const int mw = wid & 3, nw = wid >> 2;
    const int h = blockIdx.z, b = blockIdx.y;
    const int q0 = blockIdx.x * 64;
    const int hb = h * BB + b;

    load_cvt_tile(g_q + ((size_t)hb * SS + q0) * DK, sm + SM_QH, sm + SM_QL, tid);
    __syncthreads();

    uint32_t qh[4][4], ql[4][4];
    {
        uint32_t roff = (uint32_t)(mw * 16 + (lane & 15)) * ROW_B + (uint32_t)(lane >> 4) * 16;
#pragma unroll
        for (int ks = 0; ks < 4; ks++) {
            ldm_x4(qh[ks], sb + SM_QH + roff + ks * 32);
            ldm_x4(ql[ks], sb + SM_QL + roff + ks * 32);
        }
    }

    float oacc[8][4] = {};
    float rs0 = 0.0f, rs1 = 0.0f;
    const int g = lane >> 2, qq = (lane & 3) * 2;
    const int r0 = mw * 16 + g, r1 = r0 + 8;
    float* arow0 = attn ? attn + ((size_t)hb * SS + q0 + r0) * SS : (float*)0;
    float* arow1 = attn ? attn + ((size_t)hb * SS + q0 + r1) * SS : (float*)0;

    for (int kt = 0; kt < SS; kt += 64) {
        load_cvt_tile(g_k + ((size_t)hb * SS + kt) * DK, sm + SM_KH, sm + SM_KL, tid);
        load_cvt_tile(g_v + ((size_t)hb * SS + kt) * DV, sm + SM_VH, sm + SM_VL, tid);
        if (tid < 64) ((int*)(sm + SM_MSK))[tid] = g_mask[b * SS + kt + tid];
        __syncthreads();

        float sacc[4][4] = {};
        {
            const int l16 = lane & 15;
            uint32_t rbase = (uint32_t)(nw * 32 + (l16 & 7)) * ROW_B + (uint32_t)((l16 >> 3) & 1) * 16;
#pragma unroll
            for (int nt = 0; nt < 4; nt++) {
                uint32_t ro = rbase + (uint32_t)nt * (8 * ROW_B);
#pragma unroll
                for (int ks = 0; ks < 4; ks++) {
                    uint32_t co = ro + ks * 32;
                    uint32_t bh[2], bl[2];
                    ldm_x2(bh, sb + SM_KH + co);
                    ldm_x2(bl, sb + SM_KL + co);
                    mma16816(sacc[nt], qh[ks], bh);
                    mma16816(sacc[nt], ql[ks], bh);
                    mma16816(sacc[nt], qh[ks], bl);
                }
            }
        }

        uint32_t ph[4][2], pl[4][2];
        {
            const int* msk = (const int*)(sm + SM_MSK);
#pragma unroll
            for (int nt = 0; nt < 4; nt++) {
                int cb = nw * 32 + nt * 8 + qq;
                int m0 = msk[cb], m1 = msk[cb + 1];
                float e00 = m0 ? __expf(sacc[nt][0] * 0.125f) : 0.0f;
                float e01 = m1 ? __expf(sacc[nt][1] * 0.125f) : 0.0f;
                float e10 = m0 ? __expf(sacc[nt][2] * 0.125f) : 0.0f;
                float e11 = m1 ? __expf(sacc[nt][3] * 0.125f) : 0.0f;
                rs0 += e00 + e01; rs1 += e10 + e11;
                if (arow0) {
                    *(float2*)(arow0 + kt + cb) = make_float2(e00, e01);
                    *(float2*)(arow1 + kt + cb) = make_float2(e10, e11);
                }
                __nv_bfloat162 h0 = __floats2bfloat162_rn(e00, e01);
                __nv_bfloat162 h1 = __floats2bfloat162_rn(e10, e11);
                __nv_bfloat162 l0 = __floats2bfloat162_rn(e00 - __low2float(h0), e01 - __high2float(h0));
                __nv_bfloat162 l1 = __floats2bfloat162_rn(e10 - __low2float(h1), e11 - __high2float(h1));
                ph[nt][0] = bf2_bits(h0); ph[nt][1] = bf2_bits(h1);
                pl[nt][0] = bf2_bits(l0); pl[nt][1] = bf2_bits(l1);
            }
        }

        {
            const int l16 = lane & 15;
#pragma unroll
            for (int ks = 0; ks < 2; ks++) {
                uint32_t ah[4] = {ph[2*ks][0], ph[2*ks][1], ph[2*ks+1][0], ph[2*ks+1][1]};
                uint32_t al[4] = {pl[2*ks][0], pl[2*ks][1], pl[2*ks+1][0], pl[2*ks+1][1]};
                uint32_t roff = (uint32_t)(nw * 32 + ks * 16 + l16) * ROW_B;
#pragma unroll
                for (int vt = 0; vt < 8; vt++) {
                    uint32_t co = roff + vt * 16;
                    uint32_t bh[2], bl[2];
                    ldm_x2_trans(bh, sb + SM_VH + co);
                    ldm_x2_trans(bl, sb + SM_VL + co);
                    mma16816(oacc[vt], ah, bh);
                    mma16816(oacc[vt], al, bh);
                    mma16816(oacc[vt], ah, bl);
                }
            }
        }
        __syncthreads();
    }

    rs0 += __shfl_xor_sync(0xffffffffu, rs0, 1);
    rs0 += __shfl_xor_sync(0xffffffffu, rs0, 2);
    rs1 += __shfl_xor_sync(0xffffffffu, rs1, 1);
    rs1 += __shfl_xor_sync(0xffffffffu, rs1, 2);
    float* rowsum = (float*)(sm + SM_ROWSUM);
    if ((lane & 3) == 0) {
        rowsum[nw * 64 + r0] = rs0;
        rowsum[nw * 64 + r1] = rs1;
    }
    float* osh = (float*)(sm + SM_KH);
    if (nw == 1) {
#pragma unroll
        for (int vt = 0; vt < 8; vt++) {
            int c = vt * 8 + qq;
            *(float2*)(osh + r0 * 64 + c) = make_float2(oacc[vt][0], oacc[vt][1]);
            *(float2*)(osh + r1 * 64 + c) = make_float2(oacc[vt][2], oacc[vt][3]);
        }
    }
    __syncthreads();
    float* invrow = (float*)(sm + SM_INV);
    if (tid < 64) {
        float t = rowsum[tid] + rowsum[64 + tid];
        float iv = (t > 0.0f) ? (1.0f / t) : 0.0f;
        invrow[tid] = iv;
        g_rinv[(size_t)hb * SS + q0 + tid] = iv;
    }
    __syncthreads();
    if (nw == 0) {
        float iv0 = invrow[r0], iv1 = invrow[r1];
        float* p0 = g_pre + ((size_t)(b * SS + q0 + r0)) * (NH * DV) + h * DV;
        float* p1 = g_pre + ((size_t)(b * SS + q0 + r1)) * (NH * DV) + h * DV;
#pragma unroll
        for (int vt = 0; vt < 8; vt++) {
            int c = vt * 8 + qq;
            float2 t0 = *(float2*)(osh + r0 * 64 + c);
            float2 t1 = *(float2*)(osh + r1 * 64 + c);
            *(float2*)(p0 + c) = make_float2((oacc[vt][0] + t0.x) * iv0, (oacc[vt][1] + t0.y) * iv0);
            *(float2*)(p1 + c) = make_float2((oacc[vt][2] + t1.x) * iv1, (oacc[vt][3] + t1.y) * iv1);
        }
    }
}

// ---------------- attn normalization pass ----------------
__global__ __launch_bounds__(256) void norm_kernel(float* __restrict__ attn) {
    size_t i = (size_t)blockIdx.x * blockDim.x + threadIdx.x;
    size_t total4 = ATT_E / 4;
    if (i >= total4) return;
    size_t row = i / (SS / 4);
    float inv = g_rinv[row];
    float4 v = ((float4*)attn)[i];
    v.x *= inv; v.y *= inv; v.z *= inv; v.w *= inv;
    ((float4*)attn)[i] = v;
}

// ---------------- launch ----------------
extern "C" void kernel_launch(void* const* d_in, const int* in_sizes, int n_in,
                              void* d_out, int out_size) {
    const float* Q   = (const float*)d_in[0];
    const float* K   = (const float*)d_in[1];
    const float* V   = (const float*)d_in[2];
    const float* Wq  = (const float*)d_in[3];
    const float* Wk  = (const float*)d_in[4];
    const float* Wv  = (const float*)d_in[5];
    const float* Wo  = (const float*)d_in[6];
    const void*  msk = d_in[7];

    float* out = (float*)d_out;
    float* attn = nullptr;
    if ((size_t)out_size >= (size_t)OUT_E + ATT_E) attn = out + OUT_E;

    float *qp, *kp, *vp, *prep;
    cudaGetSymbolAddress((void**)&qp, g_q);
    cudaGetSymbolAddress((void**)&kp, g_k);
    cudaGetSymbolAddress((void**)&vp, g_v);
    cudaGetSymbolAddress((void**)&prep, g_pre);
    __nv_bfloat16 *xh, *xl, *wph, *wpl, *woh, *wol, *preh, *prel;
    cudaGetSymbolAddress((void**)&xh, g_xh);
    cudaGetSymbolAddress((void**)&xl, g_xl);
    cudaGetSymbolAddress((void**)&wph, g_wph);
    cudaGetSymbolAddress((void**)&wpl, g_wpl);
    cudaGetSymbolAddress((void**)&woh, g_woh);
    cudaGetSymbolAddress((void**)&wol, g_wol);
    cudaGetSymbolAddress((void**)&preh, g_preh);
    cudaGetSymbolAddress((void**)&prel, g_prel);

    cudaFuncSetAttribute(attn_mma_kernel, cudaFuncAttributeMaxDynamicSharedMemorySize, ATTN_SMEM);

    mask_kernel<<<1, 256>>>(msk, ROWS);

    // fp32 -> bf16 hi/lo prepasses
    const int X4 = ROWS * DM / 4;            // 1,048,576
    const int WP4 = NH * DM * DK / 4;        // 262,144
    const int WO4 = DM * DM / 4;             // 262,144
    cvt_kernel<<<X4 / 256, 256>>>(Q, xh + 0 * (size_t)ROWS * DM, xl + 0 * (size_t)ROWS * DM, X4);
    cvt_kernel<<<X4 / 256, 256>>>(K, xh + 1 * (size_t)ROWS * DM, xl + 1 * (size_t)ROWS * DM, X4);
    cvt_kernel<<<X4 / 256, 256>>>(V, xh + 2 * (size_t)ROWS * DM, xl + 2 * (size_t)ROWS * DM, X4);
    cvt_kernel<<<WP4 / 256, 256>>>(Wq, wph + 0 * (size_t)NH * DM * DK, wpl + 0 * (size_t)NH * DM * DK, WP4);
    cvt_kernel<<<WP4 / 256, 256>>>(Wk, wph + 1 * (size_t)NH * DM * DK, wpl + 1 * (size_t)NH * DM * DK, WP4);
    cvt_kernel<<<WP4 / 256, 256>>>(Wv, wph + 2 * (size_t)NH * DM * DK, wpl + 2 * (size_t)NH * DM * DK, WP4);
    cvt_kernel<<<WO4 / 256, 256>>>(Wo, woh, wol, WO4);

    dim3 pg(ROWS / 64, NH);
    proj_mma_kernel<<<pg, 256>>>(xh + 0 * (size_t)ROWS * DM, xl + 0 * (size_t)ROWS * DM,
                                 wph + 0 * (size_t)NH * DM * DK, wpl + 0 * (size_t)NH * DM * DK, qp);
    proj_mma_kernel<<<pg, 256>>>(xh + 1 * (size_t)ROWS * DM, xl + 1 * (size_t)ROWS * DM,
                                 wph + 1 * (size_t)NH * DM * DK, wpl + 1 * (size_t)NH * DM * DK, kp);
    proj_mma_kernel<<<pg, 256>>>(xh + 2 * (size_t)ROWS * DM, xl + 2 * (size_t)ROWS * DM,
                                 wph + 2 * (size_t)NH * DM * DK, wpl + 2 * (size_t)NH * DM * DK, vp);

    dim3 ag(SS / 64, BB, NH);
    attn_mma_kernel<<<ag, 256, ATTN_SMEM>>>(attn);

    if (attn) {
        int nblk = (int)(ATT_E / 4 / 256);
        norm_kernel<<<nblk, 256>>>(attn);
    }

    cvt_kernel<<<X4 / 256, 256>>>(prep, preh, prel, X4);
    dim3 og(ROWS / 64, DM / 64);
    outgemm_mma_kernel<<<og, 256>>>(out);
}

// round 16
// speedup vs baseline: 2.2653x; 1.0025x over previous
#include <cuda_runtime.h>
#include <cuda_bf16.h>
#include <cstdint>
#include <cstddef>

#define NH 16
#define DK 64
#define DV 64
#define DM 1024
#define BB 2
#define SS 2048

#define HB   (NH * BB)            // 32
#define ROWS (BB * SS)            // 4096
#define OUT_E (ROWS * DM)         // 4,194,304 floats
#define ATT_E ((size_t)HB * SS * SS) // 134,217,728 floats

// ---------------- scratch (no allocations allowed) ----------------
__device__ int   g_mask[ROWS];
__device__ float g_rinv[HB * SS];
// bf16 hi/lo q/k/v (written by proj_mma, read by attn)
__device__ __nv_bfloat16 g_qh[HB * SS * DK];
__device__ __nv_bfloat16 g_ql[HB * SS * DK];
__device__ __nv_bfloat16 g_kh[HB * SS * DK];
__device__ __nv_bfloat16 g_kl[HB * SS * DK];
__device__ __nv_bfloat16 g_vh[HB * SS * DV];
__device__ __nv_bfloat16 g_vl[HB * SS * DV];
// bf16 hi/lo GEMM operands
__device__ __nv_bfloat16 g_xh[3][ROWS * DM];
__device__ __nv_bfloat16 g_xl[3][ROWS * DM];
__device__ __nv_bfloat16 g_wph[3][NH * DM * DK];
__device__ __nv_bfloat16 g_wpl[3][NH * DM * DK];
__device__ __nv_bfloat16 g_woh[DM * DM];
__device__ __nv_bfloat16 g_wol[DM * DM];
__device__ __nv_bfloat16 g_preh[ROWS * NH * DV];
__device__ __nv_bfloat16 g_prel[ROWS * NH * DV];

// ================= portable PTX helpers (sm_80+ ISA) ==========
__device__ __forceinline__ uint32_t smem_u32(const void* p) {
    uint32_t a;
    asm("{ .reg .u64 t; cvta.to.shared.u64 t, %1; cvt.u32.u64 %0, t; }" : "=r"(a) : "l"(p));
    return a;
}
__device__ __forceinline__ void ldm_x4(uint32_t (&r)[4], uint32_t addr) {
    asm volatile("ldmatrix.sync.aligned.m8n8.x4.shared.b16 {%0,%1,%2,%3}, [%4];"
        : "=r"(r[0]), "=r"(r[1]), "=r"(r[2]), "=r"(r[3]) : "r"(addr));
}
__device__ __forceinline__ void ldm_x2(uint32_t (&r)[2], uint32_t addr) {
    asm volatile("ldmatrix.sync.aligned.m8n8.x2.shared.b16 {%0,%1}, [%2];"
        : "=r"(r[0]), "=r"(r[1]) : "r"(addr));
}
__device__ __forceinline__ void ldm_x2_trans(uint32_t (&r)[2], uint32_t addr) {
    asm volatile("ldmatrix.sync.aligned.m8n8.x2.trans.shared.b16 {%0,%1}, [%2];"
        : "=r"(r[0]), "=r"(r[1]) : "r"(addr));
}
__device__ __forceinline__ void mma16816(float (&d)[4], const uint32_t (&a)[4], const uint32_t (&b)[2]) {
    asm volatile("mma.sync.aligned.m16n8k16.row.col.f32.bf16.bf16.f32 "
        "{%0,%1,%2,%3}, {%4,%5,%6,%7}, {%8,%9}, {%0,%1,%2,%3};"
        : "+f"(d[0]), "+f"(d[1]), "+f"(d[2]), "+f"(d[3])
        : "r"(a[0]), "r"(a[1]), "r"(a[2]), "r"(a[3]), "r"(b[0]), "r"(b[1]));
}
__device__ __forceinline__ uint32_t bf2_bits(__nv_bfloat162 v) {
    return *reinterpret_cast<uint32_t*>(&v);
}
#define CP_ASYNC16(dst, src) \
    asm volatile("cp.async.cg.shared.global [%0], [%1], 16;" :: "r"(dst), "l"(src))
#define CP_COMMIT() asm volatile("cp.async.commit_group;" ::: "memory")
#define CP_WAIT1() asm volatile("cp.async.wait_group 1;" ::: "memory")
#define CP_WAIT0() asm volatile("cp.async.wait_group 0;" ::: "memory")

// ---------------- mask conversion (dtype-robust) ----------------
__global__ void mask_kernel(const void* mraw, int n) {
    __shared__ int mode;
    if (threadIdx.x == 0) {
        const unsigned* mi = (const unsigned*)mraw;
        const float* mf = (const float*)mraw;
        int lim = n / 4; if (lim > 1024) lim = 1024;
        int ok_i = 1, ok_f = 1;
        for (int i = 0; i < lim; i++) {
            if (mi[i] > 1u) ok_i = 0;
            float f = mf[i];
            if (!(f == 0.0f || f == 1.0f)) ok_f = 0;
            if (!ok_i && !ok_f) break;
        }
        mode = ok_i ? 1 : (ok_f ? 2 : 0);
    }
    __syncthreads();
    int md = mode;
    for (int i = threadIdx.x; i < n; i += blockDim.x) {
        int val;
        if (md == 1)      val = ((const int*)mraw)[i] != 0;
        else if (md == 2) val = ((const float*)mraw)[i] != 0.0f;
        else              val = ((const unsigned char*)mraw)[i] != 0;
        g_mask[i] = val;
    }
}

// ---------------- fp32 -> bf16 hi/lo conversion ----------------
__global__ __launch_bounds__(256) void cvt_kernel(const float* __restrict__ in,
                                                  __nv_bfloat16* __restrict__ oh,
                                                  __nv_bfloat16* __restrict__ ol, int n4) {
    int i = blockIdx.x * blockDim.x + threadIdx.x;
    if (i >= n4) return;
    float4 f = ((const float4*)in)[i];
    __nv_bfloat162 h0 = __floats2bfloat162_rn(f.x, f.y);
    __nv_bfloat162 h1 = __floats2bfloat162_rn(f.z, f.w);
    __nv_bfloat162 l0 = __floats2bfloat162_rn(f.x - __low2float(h0), f.y - __high2float(h0));
    __nv_bfloat162 l1 = __floats2bfloat162_rn(f.z - __low2float(h1), f.w - __high2float(h1));
    ((uint2*)oh)[i] = make_uint2(bf2_bits(h0), bf2_bits(h1));
    ((uint2*)ol)[i] = make_uint2(bf2_bits(l0), bf2_bits(l1));
}

// ---------------- mma GEMM tiles: 64x64 C, 8 warps ------
#define ROW_B 144
#define SXH 0
#define SXL 9216
#define SWH 18432
#define SWL 27648

// projection: Chi/Clo[((h*BB+b)*SS+s)*64 + n] (bf16 hi/lo split of fp32 product)
__global__ void __launch_bounds__(256) proj_mma_kernel(const __nv_bfloat16* __restrict__ Xh,
                                                       const __nv_bfloat16* __restrict__ Xl,
                                                       const __nv_bfloat16* __restrict__ Wh,
                                                       const __nv_bfloat16* __restrict__ Wl,
                                                       __nv_bfloat16* __restrict__ Chi,
                                                       __nv_bfloat16* __restrict__ Clo) {
    __shared__ char sm[4 * 64 * ROW_B];
    uint32_t sb = smem_u32(sm);
    const int tid = threadIdx.x, lane = tid & 31, wid = tid >> 5;
    const int mw = wid & 3, nw = wid >> 2;
    const int h = blockIdx.y;
    const int m0 = blockIdx.x * 64;
    const char* xh_g = (const char*)(Xh + (size_t)m0 * DM);
    const char* xl_g = (const char*)(Xl + (size_t)m0 * DM);
    const char* wh_g = (const char*)(Wh + (size_t)h * DM * DK);
    const char* wl_g = (const char*)(Wl + (size_t)h * DM * DK);

    float acc[4][4] = {};
    for (int k0 = 0; k0 < DM; k0 += 64) {
#pragma unroll
        for (int it = 0; it < 2; it++) {
            int i = tid + it * 256;
            int r = i >> 3, ch = (i & 7) * 16;
            size_t xo = (size_t)r * (DM * 2) + (size_t)k0 * 2 + ch;
            size_t wo = (size_t)(k0 + r) * (DK * 2) + ch;
            *(uint4*)(sm + SXH + r * ROW_B + ch) = *(const uint4*)(xh_g + xo);
            *(uint4*)(sm + SXL + r * ROW_B + ch) = *(const uint4*)(xl_g + xo);
            *(uint4*)(sm + SWH + r * ROW_B + ch) = *(const uint4*)(wh_g + wo);
            *(uint4*)(sm + SWL + r * ROW_B + ch) = *(const uint4*)(wl_g + wo);
        }
        __syncthreads();
        const int l16 = lane & 15;
#pragma unroll
        for (int ks = 0; ks < 4; ks++) {
            uint32_t ah[4], al[4];
            uint32_t aoff = (uint32_t)(mw * 16 + l16) * ROW_B + (uint32_t)(lane >> 4) * 16 + ks * 32;
            ldm_x4(ah, sb + SXH + aoff);
            ldm_x4(al, sb + SXL + aoff);
            uint32_t broff = (uint32_t)(ks * 16 + l16) * ROW_B;
#pragma unroll
            for (int nt = 0; nt < 4; nt++) {
                uint32_t co = broff + (uint32_t)(nw * 32 + nt * 8) * 2;
                uint32_t bh[2], bl[2];
                ldm_x2_trans(bh, sb + SWH + co);
                ldm_x2_trans(bl, sb + SWL + co);
                mma16816(acc[nt], ah, bh);
                mma16816(acc[nt], al, bh);
                mma16816(acc[nt], ah, bl);
            }
        }
        __syncthreads();
    }
    const int b = m0 / SS;
    const int s0 = m0 - b * SS;
    const int hb = h * BB + b;
    const int g = lane >> 2, qq = (lane & 3) * 2;
    size_t row0 = ((size_t)hb * SS + s0 + mw * 16 + g) * DK;
    size_t row1 = row0 + 8 * DK;
#pragma unroll
    for (int nt = 0; nt < 4; nt++) {
        int c = nw * 32 + nt * 8 + qq;
        __nv_bfloat162 h0 = __floats2bfloat162_rn(acc[nt][0], acc[nt][1]);
        __nv_bfloat162 l0 = __floats2bfloat162_rn(acc[nt][0] - __low2float(h0),
                                                  acc[nt][1] - __high2float(h0));
        __nv_bfloat162 h1 = __floats2bfloat162_rn(acc[nt][2], acc[nt][3]);
        __nv_bfloat162 l1 = __floats2bfloat162_rn(acc[nt][2] - __low2float(h1),
                                                  acc[nt][3] - __high2float(h1));
        *(uint32_t*)(Chi + row0 + c) = bf2_bits(h0);
        *(uint32_t*)(Clo + row0 + c) = bf2_bits(l0);
        *(uint32_t*)(Chi + row1 + c) = bf2_bits(h1);
        *(uint32_t*)(Clo + row1 + c) = bf2_bits(l1);
    }
}

// out[m][n0+n] = pre @ Wo (unchanged from round 13)
__global__ void __launch_bounds__(256) outgemm_mma_kernel(float* __restrict__ out) {
    __shared__ char sm[4 * 64 * ROW_B];
    uint32_t sb = smem_u32(sm);
    const int tid = threadIdx.x, lane = tid & 31, wid = tid >> 5;
    const int mw = wid & 3, nw = wid >> 2;
    const int m0 = blockIdx.x * 64;
    const int n0 = blockIdx.y * 64;
    const char* ah_g = (const char*)(g_preh + (size_t)m0 * DM);
    const char* al_g = (const char*)(g_prel + (size_t)m0 * DM);
    const char* bh_g = (const char*)g_woh;
    const char* bl_g = (const char*)g_wol;

    float acc[4][4] = {};
    for (int k0 = 0; k0 < DM; k0 += 64) {
#pragma unroll
        for (int it = 0; it < 2; it++) {
            int i = tid + it * 256;
            int r = i >> 3, ch = (i & 7) * 16;
            size_t ao = (size_t)r * (DM * 2) + (size_t)k0 * 2 + ch;
            size_t bo = (size_t)(k0 + r) * (DM * 2) + (size_t)n0 * 2 + ch;
            *(uint4*)(sm + SXH + r * ROW_B + ch) = *(const uint4*)(ah_g + ao);
            *(uint4*)(sm + SXL + r * ROW_B + ch) = *(const uint4*)(al_g + ao);
            *(uint4*)(sm + SWH + r * ROW_B + ch) = *(const uint4*)(bh_g + bo);
            *(uint4*)(sm + SWL + r * ROW_B + ch) = *(const uint4*)(bl_g + bo);
        }
        __syncthreads();
        const int l16 = lane & 15;
#pragma unroll
        for (int ks = 0; ks < 4; ks++) {
            uint32_t ah[4], al[4];
            uint32_t aoff = (uint32_t)(mw * 16 + l16) * ROW_B + (uint32_t)(lane >> 4) * 16 + ks * 32;
            ldm_x4(ah, sb + SXH + aoff);
            ldm_x4(al, sb + SXL + aoff);
            uint32_t broff = (uint32_t)(ks * 16 + l16) * ROW_B;
#pragma unroll
            for (int nt = 0; nt < 4; nt++) {
                uint32_t co = broff + (uint32_t)(nw * 32 + nt * 8) * 2;
                uint32_t bh[2], bl[2];
                ldm_x2_trans(bh, sb + SWH + co);
                ldm_x2_trans(bl, sb + SWL + co);
                mma16816(acc[nt], ah, bh);
                mma16816(acc[nt], al, bh);
                mma16816(acc[nt], ah, bl);
            }
        }
        __syncthreads();
    }
    const int g = lane >> 2, qq = (lane & 3) * 2;
    float* c0 = out + (size_t)(m0 + mw * 16 + g) * DM + n0;
    float* c1 = c0 + 8 * DM;
#pragma unroll
    for (int nt = 0; nt < 4; nt++) {
        int c = nw * 32 + nt * 8 + qq;
        *(float2*)(c0 + c) = make_float2(acc[nt][0], acc[nt][1]);
        *(float2*)(c1 + c) = make_float2(acc[nt][2], acc[nt][3]);
    }
}

// ---------------- attention: bf16 inputs + cp.async 2-stage pipeline ----------------
#define SM_QH 0
#define SM_QL 9216
#define SM_KV 18432            // 2 stages x 36864 (KH,KL,VH,VL @ +0,+9216,+18432,+27648)
#define STAGE_B 36864
#define SM_MSK2 92160          // 2048 ints
#define SM_ROWSUM 100352
#define SM_INV 100864
#define ATTN_SMEM 101120

__device__ __forceinline__ void prefetch_kv(uint32_t stg, const char* kh, const char* kl,
                                            const char* vh, const char* vl, int tid) {
#pragma unroll
    for (int j = 0; j < 2; j++) {
        int c = tid + j * 256;            // 512 chunks per array
        int r = c >> 3, ch = (c & 7) * 16;
        uint32_t doff = (uint32_t)r * ROW_B + ch;
        uint32_t soff = (uint32_t)r * 128 + ch;
        CP_ASYNC16(stg + 0     + doff, kh + soff);
        CP_ASYNC16(stg + 9216  + doff, kl + soff);
        CP_ASYNC16(stg + 18432 + doff, vh + soff);
        CP_ASYNC16(stg + 27648 + doff, vl + soff);
    }
}

__global__ void __launch_bounds__(256) attn_mma_kernel(float* __restrict__ attn) {
    extern __shared__ char sm[];
    uint32_t sb = smem_u32(sm);
    const int tid = threadIdx.x, lane = tid & 31, wid = tid >> 5;
    const int mw = wid & 3, nw = wid >> 2;
    const int hh = blockIdx.z, b = blockIdx.y;
    const int q0 = blockIdx.x * 64;
    const int hb = hh * BB + b;

    // Q hi/lo tiles + mask row (plain loads, once)
    {
        const char* qh_g = (const char*)(g_qh + ((size_t)hb * SS + q0) * DK);
        const char* ql_g = (const char*)(g_ql + ((size_t)hb * SS + q0) * DK);
#pragma unroll
        for (int j = 0; j < 2; j++) {
            int c = tid + j * 256;
            int r = c >> 3, ch = (c & 7) * 16;
            *(uint4*)(sm + SM_QH + r * ROW_B + ch) = *(const uint4*)(qh_g + r * 128 + ch);
            *(uint4*)(sm + SM_QL + r * ROW_B + ch) = *(const uint4*)(ql_g + r * 128 + ch);
        }
        const int4* mg = (const int4*)(g_mask + b * SS);
#pragma unroll
        for (int j = 0; j < 2; j++)
            ((int4*)(sm + SM_MSK2))[tid + j * 256] = mg[tid + j * 256];
    }

    const char* kh_g = (const char*)(g_kh + (size_t)hb * SS * DK);
    const char* kl_g = (const char*)(g_kl + (size_t)hb * SS * DK);
    const char* vh_g = (const char*)(g_vh + (size_t)hb * SS * DV);
    const char* vl_g = (const char*)(g_vl + (size_t)hb * SS * DV);

    // prefetch tile 0
    prefetch_kv(sb + SM_KV, kh_g, kl_g, vh_g, vl_g, tid);
    CP_COMMIT();
    __syncthreads();  // Q/mask visible to all

    // Q fragments
    uint32_t qh[4][4], ql[4][4];
    {
        uint32_t roff = (uint32_t)(mw * 16 + (lane & 15)) * ROW_B + (uint32_t)(lane >> 4) * 16;
#pragma unroll
        for (int ks = 0; ks < 4; ks++) {
            ldm_x4(qh[ks], sb + SM_QH + roff + ks * 32);
            ldm_x4(ql[ks], sb + SM_QL + roff + ks * 32);
        }
    }

    float oacc[8][4] = {};
    float rs0 = 0.0f, rs1 = 0.0f;
    const int g = lane >> 2, qq = (lane & 3) * 2;
    const int r0 = mw * 16 + g, r1 = r0 + 8;
    float* arow0 = attn ? attn + ((size_t)hb * SS + q0 + r0) * SS : (float*)0;
    float* arow1 = attn ? attn + ((size_t)hb * SS + q0 + r1) * SS : (float*)0;
    const int* mskall = (const int*)(sm + SM_MSK2);

    for (int it = 0; it < SS / 64; it++) {
        const int kt = it * 64;
        if (it + 1 < SS / 64) {
            uint32_t stg = sb + SM_KV + ((it + 1) & 1) * STAGE_B;
            size_t off = (size_t)(kt + 64) * DK * 2;
            prefetch_kv(stg, kh_g + off, kl_g + off, vh_g + off, vl_g + off, tid);
            CP_COMMIT();
            CP_WAIT1();
        } else {
            CP_WAIT0();
        }
        __syncthreads();
        const uint32_t stg = sb + SM_KV + (it & 1) * STAGE_B;

        // ---- scores S = Q K^T (3-pass) ----
        float sacc[4][4] = {};
        {
            const int l16 = lane & 15;
            uint32_t rbase = (uint32_t)(nw * 32 + (l16 & 7)) * ROW_B + (uint32_t)((l16 >> 3) & 1) * 16;
#pragma unroll
            for (int nt = 0; nt < 4; nt++) {
                uint32_t ro = rbase + (uint32_t)nt * (8 * ROW_B);
#pragma unroll
                for (int ks = 0; ks < 4; ks++) {
                    uint32_t co = ro + ks * 32;
                    uint32_t bh[2], bl[2];
                    ldm_x2(bh, stg + 0 + co);
                    ldm_x2(bl, stg + 9216 + co);
                    mma16816(sacc[nt], qh[ks], bh);
                    mma16816(sacc[nt], ql[ks], bh);
                    mma16816(sacc[nt], qh[ks], bl);
                }
            }
        }

        // ---- epilogue: mask + exp + attn store + rowsum + P hi/lo frags ----
        uint32_t ph[4][2], pl[4][2];
#pragma unroll
        for (int nt = 0; nt < 4; nt++) {
            int cb = nw * 32 + nt * 8 + qq;
            int m0 = mskall[kt + cb], m1 = mskall[kt + cb + 1];
            float e00 = m0 ? __expf(sacc[nt][0] * 0.125f) : 0.0f;
            float e01 = m1 ? __expf(sacc[nt][1] * 0.125f) : 0.0f;
            float e10 = m0 ? __expf(sacc[nt][2] * 0.125f) : 0.0f;
            float e11 = m1 ? __expf(sacc[nt][3] * 0.125f) : 0.0f;
            rs0 += e00 + e01; rs1 += e10 + e11;
            if (arow0) {
                *(float2*)(arow0 + kt + cb) = make_float2(e00, e01);
                *(float2*)(arow1 + kt + cb) = make_float2(e10, e11);
            }
            __nv_bfloat162 h0 = __floats2bfloat162_rn(e00, e01);
            __nv_bfloat162 h1 = __floats2bfloat162_rn(e10, e11);
            __nv_bfloat162 l0 = __floats2bfloat162_rn(e00 - __low2float(h0), e01 - __high2float(h0));
            __nv_bfloat162 l1 = __floats2bfloat162_rn(e10 - __low2float(h1), e11 - __high2float(h1));
            ph[nt][0] = bf2_bits(h0); ph[nt][1] = bf2_bits(h1);
            pl[nt][0] = bf2_bits(l0); pl[nt][1] = bf2_bits(l1);
        }

        // ---- PV: O += P V (3-pass) ----
        {
            const int l16 = lane & 15;
#pragma unroll
            for (int ks = 0; ks < 2; ks++) {
                uint32_t ah[4] = {ph[2*ks][0], ph[2*ks][1], ph[2*ks+1][0], ph[2*ks+1][1]};
                uint32_t al[4] = {pl[2*ks][0], pl[2*ks][1], pl[2*ks+1][0], pl[2*ks+1][1]};
                uint32_t roff = (uint32_t)(nw * 32 + ks * 16 + l16) * ROW_B;
#pragma unroll
                for (int vt = 0; vt < 8; vt++) {
                    uint32_t co = roff + vt * 16;
                    uint32_t bh[2], bl[2];
                    ldm_x2_trans(bh, stg + 18432 + co);
                    ldm_x2_trans(bl, stg + 27648 + co);
                    mma16816(oacc[vt], ah, bh);
                    mma16816(oacc[vt], al, bh);
                    mma16816(oacc[vt], ah, bl);
                }
            }
        }
        __syncthreads();
    }

    // ---- rowsum reduction + O exchange + normalized hi/lo pre store ----
    rs0 += __shfl_xor_sync(0xffffffffu, rs0, 1);
    rs0 += __shfl_xor_sync(0xffffffffu, rs0, 2);
    rs1 += __shfl_xor_sync(0xffffffffu, rs1, 1);
    rs1 += __shfl_xor_sync(0xffffffffu, rs1, 2);
    float* rowsum = (float*)(sm + SM_ROWSUM);
    if ((lane & 3) == 0) {
        rowsum[nw * 64 + r0] = rs0;
        rowsum[nw * 64 + r1] = rs1;
    }
    float* osh = (float*)(sm + SM_KV);
    if (nw == 1) {
#pragma unroll
        for (int vt = 0; vt < 8; vt++) {
            int c = vt * 8 + qq;
            *(float2*)(osh + r0 * 64 + c) = make_float2(oacc[vt][0], oacc[vt][1]);
            *(float2*)(osh + r1 * 64 + c) = make_float2(oacc[vt][2], oacc[vt][3]);
        }
    }
    __syncthreads();
    float* invrow = (float*)(sm + SM_INV);
    if (tid < 64) {
        float t = rowsum[tid] + rowsum[64 + tid];
        float iv = (t > 0.0f) ? (1.0f / t) : 0.0f;
        invrow[tid] = iv;
        g_rinv[(size_t)hb * SS + q0 + tid] = iv;
    }
    __syncthreads();
    if (nw == 0) {
        float iv0 = invrow[r0], iv1 = invrow[r1];
        size_t p0 = ((size_t)(b * SS + q0 + r0)) * (NH * DV) + hh * DV;
        size_t p1 = ((size_t)(b * SS + q0 + r1)) * (NH * DV) + hh * DV;
#pragma unroll
        for (int vt = 0; vt < 8; vt++) {
            int c = vt * 8 + qq;
            float2 t0 = *(float2*)(osh + r0 * 64 + c);
            float2 t1 = *(float2*)(osh + r1 * 64 + c);
            float f00 = (oacc[vt][0] + t0.x) * iv0, f01 = (oacc[vt][1] + t0.y) * iv0;
            float f10 = (oacc[vt][2] + t1.x) * iv1, f11 = (oacc[vt][3] + t1.y) * iv1;
            __nv_bfloat162 h0 = __floats2bfloat162_rn(f00, f01);
            __nv_bfloat162 l0 = __floats2bfloat162_rn(f00 - __low2float(h0), f01 - __high2float(h0));
            __nv_bfloat162 h1 = __floats2bfloat162_rn(f10, f11);
            __nv_bfloat162 l1 = __floats2bfloat162_rn(f10 - __low2float(h1), f11 - __high2float(h1));
            *(uint32_t*)(g_preh + p0 + c) = bf2_bits(h0);
            *(uint32_t*)(g_prel + p0 + c) = bf2_bits(l0);
            *(uint32_t*)(g_preh + p1 + c) = bf2_bits(h1);
            *(uint32_t*)(g_prel + p1 + c) = bf2_bits(l1);
        }
    }
}

// ---------------- attn normalization pass ----------------
__global__ __launch_bounds__(256) void norm_kernel(float* __restrict__ attn) {
    size_t i = (size_t)blockIdx.x * blockDim.x + threadIdx.x;
    size_t total4 = ATT_E / 4;
    if (i >= total4) return;
    size_t row = i / (SS / 4);
    float inv = g_rinv[row];
    float4 v = ((float4*)attn)[i];
    v.x *= inv; v.y *= inv; v.z *= inv; v.w *= inv;
    ((float4*)attn)[i] = v;
}

// ---------------- launch ----------------
extern "C" void kernel_launch(void* const* d_in, const int* in_sizes, int n_in,
                              void* d_out, int out_size) {
    const float* Q   = (const float*)d_in[0];
    const float* K   = (const float*)d_in[1];
    const float* V   = (const float*)d_in[2];
    const float* Wq  = (const float*)d_in[3];
    const float* Wk  = (const float*)d_in[4];
    const float* Wv  = (const float*)d_in[5];
    const float* Wo  = (const float*)d_in[6];
    const void*  msk = d_in[7];

    float* out = (float*)d_out;
    float* attn = nullptr;
    if ((size_t)out_size >= (size_t)OUT_E + ATT_E) attn = out + OUT_E;

    __nv_bfloat16 *qh, *ql, *kh, *kl, *vh, *vl, *xh, *xl, *wph, *wpl;
    cudaGetSymbolAddress((void**)&qh, g_qh);
    cudaGetSymbolAddress((void**)&ql, g_ql);
    cudaGetSymbolAddress((void**)&kh, g_kh);
    cudaGetSymbolAddress((void**)&kl, g_kl);
    cudaGetSymbolAddress((void**)&vh, g_vh);
    cudaGetSymbolAddress((void**)&vl, g_vl);
    cudaGetSymbolAddress((void**)&xh, g_xh);
    cudaGetSymbolAddress((void**)&xl, g_xl);
    cudaGetSymbolAddress((void**)&wph, g_wph);
    cudaGetSymbolAddress((void**)&wpl, g_wpl);
    __nv_bfloat16 *woh, *wol;
    cudaGetSymbolAddress((void**)&woh, g_woh);
    cudaGetSymbolAddress((void**)&wol, g_wol);

    cudaFuncSetAttribute(attn_mma_kernel, cudaFuncAttributeMaxDynamicSharedMemorySize, ATTN_SMEM);

    mask_kernel<<<1, 256>>>(msk, ROWS);

    const int X4 = ROWS * DM / 4;
    const int WP4 = NH * DM * DK / 4;
    const int WO4 = DM * DM / 4;
    cvt_kernel<<<X4 / 256, 256>>>(Q, xh + 0 * (size_t)ROWS * DM, xl + 0 * (size_t)ROWS * DM, X4);
    cvt_kernel<<<X4 / 256, 256>>>(K, xh + 1 * (size_t)ROWS * DM, xl + 1 * (size_t)ROWS * DM, X4);
    cvt_kernel<<<X4 / 256, 256>>>(V, xh + 2 * (size_t)ROWS * DM, xl + 2 * (size_t)ROWS * DM, X4);
    cvt_kernel<<<WP4 / 256, 256>>>(Wq, wph + 0 * (size_t)NH * DM * DK, wpl + 0 * (size_t)NH * DM * DK, WP4);
    cvt_kernel<<<WP4 / 256, 256>>>(Wk, wph + 1 * (size_t)NH * DM * DK, wpl + 1 * (size_t)NH * DM * DK, WP4);
    cvt_kernel<<<WP4 / 256, 256>>>(Wv, wph + 2 * (size_t)NH * DM * DK, wpl + 2 * (size_t)NH * DM * DK, WP4);
    cvt_kernel<<<WO4 / 256, 256>>>(Wo, woh, wol, WO4);

    dim3 pg(ROWS / 64, NH);
    proj_mma_kernel<<<pg, 256>>>(xh + 0 * (size_t)ROWS * DM, xl + 0 * (size_t)ROWS * DM,
                                 wph + 0 * (size_t)NH * DM * DK, wpl + 0 * (size_t)NH * DM * DK, qh, ql);
    proj_mma_kernel<<<pg, 256>>>(xh + 1 * (size_t)ROWS * DM, xl + 1 * (size_t)ROWS * DM,
                                 wph + 1 * (size_t)NH * DM * DK, wpl + 1 * (size_t)NH * DM * DK, kh, kl);
    proj_mma_kernel<<<pg, 256>>>(xh + 2 * (size_t)ROWS * DM, xl + 2 * (size_t)ROWS * DM,
                                 wph + 2 * (size_t)NH * DM * DK, wpl + 2 * (size_t)NH * DM * DK, vh, vl);

    dim3 ag(SS / 64, BB, NH);
    attn_mma_kernel<<<ag, 256, ATTN_SMEM>>>(attn);

    if (attn) {
        int nblk = (int)(ATT_E / 4 / 256);
        norm_kernel<<<nblk, 256>>>(attn);
    }

    dim3 og(ROWS / 64, DM / 64);
    outgemm_mma_kernel<<<og, 256>>>(out);
}